// round 1
// baseline (speedup 1.0000x reference)
#include <cuda_runtime.h>
#include <cstdint>

// ---------------------------------------------------------------------------
// LatentAttention: B=2, T=2048, C=1024, H=16, Dh=64, L=64
//   qc = x @ Wqc + bqc        (Wqc = Wq folded with per-head Wc)
//   k  = x @ Wk  + bk
//   v  = x @ Wv  + bv
//   y  = causal-softmax(qc k^T / 8) v      (flash, per (b,h))
//   out = y @ Wo + bo
// ---------------------------------------------------------------------------

#define BDIM 2
#define TDIM 2048
#define CDIM 1024
#define HN   16
#define LDIM 64
#define MROWS (BDIM*TDIM)   // 4096
#define NEG_INF_F (__int_as_float(0xff800000))

// scratch (no cudaMalloc allowed)
__device__ float g_Wqc[CDIM*CDIM];
__device__ float g_bqc[CDIM];
__device__ float g_qc[MROWS*CDIM];
__device__ float g_k [MROWS*CDIM];
__device__ float g_v [MROWS*CDIM];
__device__ float g_y [MROWS*CDIM];

// ---------------------------------------------------------------------------
// Fold Wc into Wq:  Wqc[c, h*64+l] = sum_d Wq[c, h*64+d] * Wc[d, l]
// ---------------------------------------------------------------------------
__global__ __launch_bounds__(256) void prep_wqc(const float* __restrict__ Wq,
                                                const float* __restrict__ Wc) {
    __shared__ float Wcs[64*64];
    const int tid = threadIdx.x;
    for (int i = tid; i < 64*64; i += 256) Wcs[i] = Wc[i];
    __syncthreads();
    const int gid = blockIdx.x * 256 + tid;      // 0..1024*1024-1
    const int c   = gid >> 10;
    const int col = gid & 1023;
    const int h   = col >> 6;
    const int l   = col & 63;
    const float* wrow = Wq + c*CDIM + h*64;
    float acc = 0.f;
#pragma unroll
    for (int d = 0; d < 64; d++) acc += wrow[d] * Wcs[d*64 + l];
    g_Wqc[gid] = acc;
}

__global__ void prep_bqc(const float* __restrict__ bq,
                         const float* __restrict__ Wc) {
    const int col = blockIdx.x * blockDim.x + threadIdx.x;   // 0..1023
    const int h = col >> 6, l = col & 63;
    float acc = 0.f;
#pragma unroll
    for (int d = 0; d < 64; d++) acc += bq[h*64 + d] * Wc[d*64 + l];
    g_bqc[col] = acc;
}

// ---------------------------------------------------------------------------
// SGEMM: C[M,N] = A[M,K] @ B[K,N] + bias[N]
// 128x128 block tile, BK=8, 8x8 per thread, 256 threads.
// M%128==0, N%128==0, K%8==0 (here 4096,1024,1024).
// ---------------------------------------------------------------------------
__global__ __launch_bounds__(256) void sgemm_bias(
    const float* __restrict__ A, const float* __restrict__ B,
    const float* __restrict__ bias, float* __restrict__ C,
    int M, int N, int K)
{
    __shared__ float As[8][128];
    __shared__ float Bs[8][128];

    const int tid  = threadIdx.x;
    const int brow = blockIdx.y * 128;
    const int bcol = blockIdx.x * 128;

    const int aRow = tid >> 1;            // 0..127
    const int aCol = (tid & 1) << 2;      // 0 or 4
    const int bRow = tid >> 5;            // 0..7
    const int bCol = (tid & 31) << 2;     // 0..124

    const int ty = tid >> 4;              // 0..15
    const int tx = tid & 15;              // 0..15

    const float* Ag = A + (size_t)brow * K;
    const float* Bg = B + bcol;

    float acc[8][8];
#pragma unroll
    for (int i = 0; i < 8; i++)
#pragma unroll
        for (int j = 0; j < 8; j++) acc[i][j] = 0.f;

    float rM[8], rN[8];

    for (int k0 = 0; k0 < K; k0 += 8) {
        float4 a4 = *(const float4*)(Ag + (size_t)aRow * K + k0 + aCol);
        As[aCol+0][aRow] = a4.x;
        As[aCol+1][aRow] = a4.y;
        As[aCol+2][aRow] = a4.z;
        As[aCol+3][aRow] = a4.w;
        *(float4*)(&Bs[bRow][bCol]) =
            *(const float4*)(Bg + (size_t)(k0 + bRow) * N + bCol);
        __syncthreads();

#pragma unroll
        for (int kk = 0; kk < 8; kk++) {
            *(float4*)(rM)     = *(const float4*)(&As[kk][ty*8]);
            *(float4*)(rM + 4) = *(const float4*)(&As[kk][ty*8 + 4]);
            *(float4*)(rN)     = *(const float4*)(&Bs[kk][tx*8]);
            *(float4*)(rN + 4) = *(const float4*)(&Bs[kk][tx*8 + 4]);
#pragma unroll
            for (int i = 0; i < 8; i++)
#pragma unroll
                for (int j = 0; j < 8; j++) acc[i][j] += rM[i] * rN[j];
        }
        __syncthreads();
    }

    float bterm[8];
#pragma unroll
    for (int j = 0; j < 8; j++) bterm[j] = bias[bcol + tx*8 + j];

#pragma unroll
    for (int i = 0; i < 8; i++) {
        float* crow = C + (size_t)(brow + ty*8 + i) * N + bcol + tx*8;
        float4 o0 = make_float4(acc[i][0] + bterm[0], acc[i][1] + bterm[1],
                                acc[i][2] + bterm[2], acc[i][3] + bterm[3]);
        float4 o1 = make_float4(acc[i][4] + bterm[4], acc[i][5] + bterm[5],
                                acc[i][6] + bterm[6], acc[i][7] + bterm[7]);
        *(float4*)(crow)     = o0;
        *(float4*)(crow + 4) = o1;
    }
}

// ---------------------------------------------------------------------------
// Flash attention, fp32. One block = one (b,h) x one 64-row Q tile.
// 256 threads: thread (r = tid/4, seg = tid%4) owns S/O[r, seg*16 .. +15].
// Causal: iterate k-tiles 0..qt, mask only the diagonal tile.
// Smem: QT[64][64] (d-major), KT[64][64] (d-major), Vs[64][64] = 48 KB.
// P is exchanged through warp shuffles (4 lanes per row), no P smem.
// ---------------------------------------------------------------------------
__device__ __forceinline__ void ld16(float* dst, const float* src) {
    float4 a = *(const float4*)(src);
    float4 b = *(const float4*)(src + 4);
    float4 c = *(const float4*)(src + 8);
    float4 d = *(const float4*)(src + 12);
    dst[0]=a.x; dst[1]=a.y; dst[2]=a.z;  dst[3]=a.w;
    dst[4]=b.x; dst[5]=b.y; dst[6]=b.z;  dst[7]=b.w;
    dst[8]=c.x; dst[9]=c.y; dst[10]=c.z; dst[11]=c.w;
    dst[12]=d.x; dst[13]=d.y; dst[14]=d.z; dst[15]=d.w;
}

__global__ __launch_bounds__(256) void flash_attn(
    const float* __restrict__ Q, const float* __restrict__ K,
    const float* __restrict__ V, float* __restrict__ Y)
{
    __shared__ float QT[64*64];
    __shared__ float KT[64*64];
    __shared__ float Vs[64*64];

    const int tid = threadIdx.x;
    const int qt  = blockIdx.x;            // q tile 0..31
    const int bh  = blockIdx.y;            // 0..31
    const int b   = bh >> 4;
    const int h   = bh & 15;
    const int r   = tid >> 2;              // 0..63 (q row in tile)
    const int seg = tid & 3;               // 0..3
    const int c0  = seg << 4;
    const int lane  = tid & 31;
    const int gbase = lane & ~3;           // base lane of the 4-lane row group

    const size_t base = ((size_t)b * TDIM) * CDIM + h * 64;

    // load Q tile transposed: QT[d][row]
    for (int i = tid; i < 64*16; i += 256) {
        const int row = i >> 4;
        const int d4  = (i & 15) << 2;
        float4 q4 = *(const float4*)(Q + base + (size_t)(qt*64 + row)*CDIM + d4);
        QT[(d4+0)*64 + row] = q4.x;
        QT[(d4+1)*64 + row] = q4.y;
        QT[(d4+2)*64 + row] = q4.z;
        QT[(d4+3)*64 + row] = q4.w;
    }

    float o[16];
#pragma unroll
    for (int j = 0; j < 16; j++) o[j] = 0.f;
    float m = NEG_INF_F, l = 0.f;

    for (int kt = 0; kt <= qt; kt++) {
        __syncthreads();   // prior-tile reads done (and QT ready on iter 0)

        // load K tile transposed (KT[d][row]) and V tile (Vs[row][d])
        for (int i = tid; i < 64*16; i += 256) {
            const int row = i >> 4;
            const int d4  = (i & 15) << 2;
            const size_t goff = base + (size_t)(kt*64 + row)*CDIM + d4;
            float4 k4 = *(const float4*)(K + goff);
            KT[(d4+0)*64 + row] = k4.x;
            KT[(d4+1)*64 + row] = k4.y;
            KT[(d4+2)*64 + row] = k4.z;
            KT[(d4+3)*64 + row] = k4.w;
            *(float4*)(&Vs[row*64 + d4]) = *(const float4*)(V + goff);
        }
        __syncthreads();

        // S[r, c0..c0+15] = Q[r,:] . K[c,:]
        float s[16];
#pragma unroll
        for (int j = 0; j < 16; j++) s[j] = 0.f;

#pragma unroll 4
        for (int d = 0; d < 64; d++) {
            const float qv = QT[d*64 + r];
            float kreg[16];
            ld16(kreg, &KT[d*64 + c0]);
#pragma unroll
            for (int j = 0; j < 16; j++) s[j] += qv * kreg[j];
        }

        const float scale = 0.125f;
        if (kt == qt) {
#pragma unroll
            for (int j = 0; j < 16; j++)
                s[j] = (c0 + j > r) ? NEG_INF_F : s[j] * scale;
        } else {
#pragma unroll
            for (int j = 0; j < 16; j++) s[j] *= scale;
        }

        // online softmax (row = 4 adjacent lanes)
        float tmax = s[0];
#pragma unroll
        for (int j = 1; j < 16; j++) tmax = fmaxf(tmax, s[j]);
        tmax = fmaxf(tmax, __shfl_xor_sync(0xffffffffu, tmax, 1));
        tmax = fmaxf(tmax, __shfl_xor_sync(0xffffffffu, tmax, 2));

        const float mnew = fmaxf(m, tmax);
        const float corr = __expf(m - mnew);
        float psum = 0.f;
#pragma unroll
        for (int j = 0; j < 16; j++) {
            float p = __expf(s[j] - mnew);   // exp(-inf)=0 handles the mask
            s[j] = p;
            psum += p;
        }
        psum += __shfl_xor_sync(0xffffffffu, psum, 1);
        psum += __shfl_xor_sync(0xffffffffu, psum, 2);
        l = l * corr + psum;
        m = mnew;
#pragma unroll
        for (int j = 0; j < 16; j++) o[j] *= corr;

        // O[r, c0..] += P[r, :] @ V[:, c0..]  (P via shuffles from row group)
#pragma unroll
        for (int src = 0; src < 4; src++) {
#pragma unroll
            for (int jj = 0; jj < 16; jj++) {
                const float p = __shfl_sync(0xffffffffu, s[jj], gbase + src);
                float vreg[16];
                ld16(vreg, &Vs[(src*16 + jj)*64 + c0]);
#pragma unroll
                for (int j = 0; j < 16; j++) o[j] += p * vreg[j];
            }
        }
    }

    const float inv = 1.f / l;
    float* yp = Y + base + (size_t)(qt*64 + r)*CDIM + c0;
    *(float4*)(yp)      = make_float4(o[0]*inv,  o[1]*inv,  o[2]*inv,  o[3]*inv);
    *(float4*)(yp + 4)  = make_float4(o[4]*inv,  o[5]*inv,  o[6]*inv,  o[7]*inv);
    *(float4*)(yp + 8)  = make_float4(o[8]*inv,  o[9]*inv,  o[10]*inv, o[11]*inv);
    *(float4*)(yp + 12) = make_float4(o[12]*inv, o[13]*inv, o[14]*inv, o[15]*inv);
}

// ---------------------------------------------------------------------------
extern "C" void kernel_launch(void* const* d_in, const int* in_sizes, int n_in,
                              void* d_out, int out_size) {
    const float* x  = (const float*)d_in[0];
    const float* Wq = (const float*)d_in[1];
    const float* bq = (const float*)d_in[2];
    const float* Wk = (const float*)d_in[3];
    const float* bk = (const float*)d_in[4];
    const float* Wv = (const float*)d_in[5];
    const float* bv = (const float*)d_in[6];
    const float* Wo = (const float*)d_in[7];
    const float* bo = (const float*)d_in[8];
    const float* Wc = (const float*)d_in[9];
    float* out = (float*)d_out;

    float *wqc, *bqc, *qc, *kb, *vb, *yb;
    cudaGetSymbolAddress((void**)&wqc, g_Wqc);
    cudaGetSymbolAddress((void**)&bqc, g_bqc);
    cudaGetSymbolAddress((void**)&qc,  g_qc);
    cudaGetSymbolAddress((void**)&kb,  g_k);
    cudaGetSymbolAddress((void**)&vb,  g_v);
    cudaGetSymbolAddress((void**)&yb,  g_y);

    prep_wqc<<<(CDIM*CDIM)/256, 256>>>(Wq, Wc);
    prep_bqc<<<CDIM/256, 256>>>(bq, Wc);

    dim3 gg(CDIM/128, MROWS/128);   // (8, 32)
    sgemm_bias<<<gg, 256>>>(x, wqc, bqc, qc, MROWS, CDIM, CDIM);
    sgemm_bias<<<gg, 256>>>(x, Wk,  bk,  kb, MROWS, CDIM, CDIM);
    sgemm_bias<<<gg, 256>>>(x, Wv,  bv,  vb, MROWS, CDIM, CDIM);

    flash_attn<<<dim3(TDIM/64, BDIM*HN), 256>>>(qc, kb, vb, yb);

    sgemm_bias<<<gg, 256>>>(yb, Wo, bo, out, MROWS, CDIM, CDIM);
}

// round 8
// speedup vs baseline: 1.9803x; 1.9803x over previous
#include <cuda_runtime.h>
#include <cstdint>

// ---------------------------------------------------------------------------
// LatentAttention: B=2, T=2048, C=1024, H=16, Dh=64, L=64
//   qc = x @ Wqc + bqc        (Wqc = Wq folded with per-head Wc)
//   k  = x @ Wk  + bk
//   v  = x @ Wv  + bv
//   y  = causal-softmax(qc k^T / 8) v      (flash, per (b,h))
//   out = y @ Wo + bo
// ---------------------------------------------------------------------------

#define BDIM 2
#define TDIM 2048
#define CDIM 1024
#define HN   16
#define LDIM 64
#define MROWS (BDIM*TDIM)   // 4096
#define NEG_INF_F (__int_as_float(0xff800000))

// scratch (no cudaMalloc allowed)
__device__ float g_Wqc[CDIM*CDIM];
__device__ float g_bqc[CDIM];
__device__ float g_qc[MROWS*CDIM];
__device__ float g_k [MROWS*CDIM];
__device__ float g_v [MROWS*CDIM];
__device__ float g_y [MROWS*CDIM];

// ---------------------------------------------------------------------------
// Fold Wc into Wq:  Wqc[c, h*64+l] = sum_d Wq[c, h*64+d] * Wc[d, l]
// ---------------------------------------------------------------------------
__global__ __launch_bounds__(256) void prep_wqc(const float* __restrict__ Wq,
                                                const float* __restrict__ Wc) {
    __shared__ float Wcs[64*64];
    const int tid = threadIdx.x;
    for (int i = tid; i < 64*64; i += 256) Wcs[i] = Wc[i];
    __syncthreads();
    const int gid = blockIdx.x * 256 + tid;      // 0..1024*1024-1
    const int c   = gid >> 10;
    const int col = gid & 1023;
    const int h   = col >> 6;
    const int l   = col & 63;
    const float* wrow = Wq + c*CDIM + h*64;
    float acc = 0.f;
#pragma unroll
    for (int d = 0; d < 64; d++) acc += wrow[d] * Wcs[d*64 + l];
    g_Wqc[gid] = acc;
}

__global__ void prep_bqc(const float* __restrict__ bq,
                         const float* __restrict__ Wc) {
    const int col = blockIdx.x * blockDim.x + threadIdx.x;   // 0..1023
    const int h = col >> 6, l = col & 63;
    float acc = 0.f;
#pragma unroll
    for (int d = 0; d < 64; d++) acc += bq[h*64 + d] * Wc[d*64 + l];
    g_bqc[col] = acc;
}

// ---------------------------------------------------------------------------
// SGEMM: C[M,N] = A[M,K] @ B[K,N] + bias[N]
// 128x128 block tile, BK=8, 8x8 per thread, 256 threads.
// Global loads for tile k+1 prefetched into registers during compute of tile k.
// ---------------------------------------------------------------------------
__global__ __launch_bounds__(256) void sgemm_bias(
    const float* __restrict__ A, const float* __restrict__ B,
    const float* __restrict__ bias, float* __restrict__ C,
    int M, int N, int K)
{
    __shared__ float As[8][128];
    __shared__ float Bs[8][128];

    const int tid  = threadIdx.x;
    const int brow = blockIdx.y * 128;
    const int bcol = blockIdx.x * 128;

    const int aRow = tid >> 1;            // 0..127
    const int aCol = (tid & 1) << 2;      // 0 or 4
    const int bRow = tid >> 5;            // 0..7
    const int bCol = (tid & 31) << 2;     // 0..124

    const int ty = tid >> 4;              // 0..15
    const int tx = tid & 15;              // 0..15

    const float* Aptr = A + (size_t)(brow + aRow) * K + aCol;
    const float* Bptr = B + (size_t)bRow * N + bcol + bCol;

    float acc[8][8];
#pragma unroll
    for (int i = 0; i < 8; i++)
#pragma unroll
        for (int j = 0; j < 8; j++) acc[i][j] = 0.f;

    float rM[8], rN[8];

    float4 a_pf = *(const float4*)(Aptr);
    float4 b_pf = *(const float4*)(Bptr);

    for (int k0 = 0; k0 < K; k0 += 8) {
        As[aCol+0][aRow] = a_pf.x;
        As[aCol+1][aRow] = a_pf.y;
        As[aCol+2][aRow] = a_pf.z;
        As[aCol+3][aRow] = a_pf.w;
        *(float4*)(&Bs[bRow][bCol]) = b_pf;
        __syncthreads();

        if (k0 + 8 < K) {
            a_pf = *(const float4*)(Aptr + k0 + 8);
            b_pf = *(const float4*)(Bptr + (size_t)(k0 + 8) * N);
        }

#pragma unroll
        for (int kk = 0; kk < 8; kk++) {
            *(float4*)(rM)     = *(const float4*)(&As[kk][ty*8]);
            *(float4*)(rM + 4) = *(const float4*)(&As[kk][ty*8 + 4]);
            *(float4*)(rN)     = *(const float4*)(&Bs[kk][tx*8]);
            *(float4*)(rN + 4) = *(const float4*)(&Bs[kk][tx*8 + 4]);
#pragma unroll
            for (int i = 0; i < 8; i++)
#pragma unroll
                for (int j = 0; j < 8; j++) acc[i][j] += rM[i] * rN[j];
        }
        __syncthreads();
    }

    float bterm[8];
#pragma unroll
    for (int j = 0; j < 8; j++) bterm[j] = bias[bcol + tx*8 + j];

#pragma unroll
    for (int i = 0; i < 8; i++) {
        float* crow = C + (size_t)(brow + ty*8 + i) * N + bcol + tx*8;
        float4 o0 = make_float4(acc[i][0] + bterm[0], acc[i][1] + bterm[1],
                                acc[i][2] + bterm[2], acc[i][3] + bterm[3]);
        float4 o1 = make_float4(acc[i][4] + bterm[4], acc[i][5] + bterm[5],
                                acc[i][6] + bterm[6], acc[i][7] + bterm[7]);
        *(float4*)(crow)     = o0;
        *(float4*)(crow + 4) = o1;
    }
}

// ---------------------------------------------------------------------------
// Flash attention, fp32, register-blocked.
// One block = one (b,h) x one 128-row Q tile; K/V tiles of 64.
// 256 threads as 32(ty) x 8(tx); each thread owns S/O[4 rows][8 cols].
// smem: QT[64][132] d-major (128 q-rows + pad!), KT[64][72] d-major,
//       Vs[64][72] row-major, P[128][68]  -> 103 KB dynamic smem, 2 CTA/SM.
// ---------------------------------------------------------------------------
#define QT_S 132   // >= 128 q-rows per tile (was 72: OOB corruption bug)
#define KT_S 72
#define VS_S 72
#define P_S  68
#define FLASH_SMEM ((64*QT_S + 64*KT_S + 64*VS_S + 128*P_S) * 4)

__global__ __launch_bounds__(256, 2) void flash_attn(
    const float* __restrict__ Q, const float* __restrict__ K,
    const float* __restrict__ V, float* __restrict__ Y)
{
    extern __shared__ float sm[];
    float* QT = sm;                  // [64][QT_S]
    float* KT = QT + 64*QT_S;        // [64][KT_S]
    float* Vs = KT + 64*KT_S;        // [64][VS_S]
    float* P  = Vs + 64*VS_S;        // [128][P_S]

    const int tid = threadIdx.x;
    const int qt  = (gridDim.x - 1) - blockIdx.x;   // heavy tiles first
    const int bh  = blockIdx.y;                     // 0..31
    const int b   = bh >> 4;
    const int h   = bh & 15;
    const int ty  = tid >> 3;             // 0..31  (4 q rows each)
    const int tx  = tid & 7;              // 0..7   (8 cols each)
    const int r0  = ty << 2;
    const int c0  = tx << 3;

    const size_t base = ((size_t)b * TDIM) * CDIM + h * 64;

    // load Q tile transposed: QT[d][row], rows qt*128 .. +127
    for (int i = tid; i < 128*16; i += 256) {
        const int row = i >> 4;
        const int d4  = (i & 15) << 2;
        float4 q4 = *(const float4*)(Q + base + (size_t)(qt*128 + row)*CDIM + d4);
        QT[(d4+0)*QT_S + row] = q4.x;
        QT[(d4+1)*QT_S + row] = q4.y;
        QT[(d4+2)*QT_S + row] = q4.z;
        QT[(d4+3)*QT_S + row] = q4.w;
    }

    float o[4][8];
#pragma unroll
    for (int i = 0; i < 4; i++)
#pragma unroll
        for (int j = 0; j < 8; j++) o[i][j] = 0.f;
    float m[4], l[4];
#pragma unroll
    for (int i = 0; i < 4; i++) { m[i] = NEG_INF_F; l[i] = 0.f; }

    const int kt_end = 2*qt + 1;
    for (int kt = 0; kt <= kt_end; kt++) {
        __syncthreads();   // prev PV reads of Vs/P done; QT ready on iter 0

        // load K tile (transposed -> KT[d][col]) and V tile (Vs[row][d])
        for (int i = tid; i < 64*16; i += 256) {
            const int row = i >> 4;
            const int d4  = (i & 15) << 2;
            const size_t goff = base + (size_t)(kt*64 + row)*CDIM + d4;
            float4 k4 = *(const float4*)(K + goff);
            KT[(d4+0)*KT_S + row] = k4.x;
            KT[(d4+1)*KT_S + row] = k4.y;
            KT[(d4+2)*KT_S + row] = k4.z;
            KT[(d4+3)*KT_S + row] = k4.w;
            *(float4*)(&Vs[row*VS_S + d4]) = *(const float4*)(V + goff);
        }
        __syncthreads();

        // S[4][8] = Q rows . K cols
        float s[4][8];
#pragma unroll
        for (int i = 0; i < 4; i++)
#pragma unroll
            for (int j = 0; j < 8; j++) s[i][j] = 0.f;

#pragma unroll 2
        for (int d = 0; d < 64; d++) {
            float4 q4 = *(const float4*)(&QT[d*QT_S + r0]);
            float4 k0v = *(const float4*)(&KT[d*KT_S + c0]);
            float4 k1v = *(const float4*)(&KT[d*KT_S + c0 + 4]);
            const float qr[4] = {q4.x, q4.y, q4.z, q4.w};
            const float kc[8] = {k0v.x, k0v.y, k0v.z, k0v.w,
                                 k1v.x, k1v.y, k1v.z, k1v.w};
#pragma unroll
            for (int i = 0; i < 4; i++)
#pragma unroll
                for (int j = 0; j < 8; j++) s[i][j] += qr[i] * kc[j];
        }

        const float scale = 0.125f;
        if (kt >= 2*qt) {   // diagonal tiles: apply causal mask
#pragma unroll
            for (int i = 0; i < 4; i++) {
                const int grow = qt*128 + r0 + i;
#pragma unroll
                for (int j = 0; j < 8; j++) {
                    const int gcol = kt*64 + c0 + j;
                    s[i][j] = (gcol > grow) ? NEG_INF_F : s[i][j] * scale;
                }
            }
        } else {
#pragma unroll
            for (int i = 0; i < 4; i++)
#pragma unroll
                for (int j = 0; j < 8; j++) s[i][j] *= scale;
        }

        // online softmax per row (reduce over 8 tx lanes; tx = low 3 lane bits)
#pragma unroll
        for (int i = 0; i < 4; i++) {
            float rmax = s[i][0];
#pragma unroll
            for (int j = 1; j < 8; j++) rmax = fmaxf(rmax, s[i][j]);
            rmax = fmaxf(rmax, __shfl_xor_sync(0xffffffffu, rmax, 1));
            rmax = fmaxf(rmax, __shfl_xor_sync(0xffffffffu, rmax, 2));
            rmax = fmaxf(rmax, __shfl_xor_sync(0xffffffffu, rmax, 4));

            const float mnew = fmaxf(m[i], rmax);
            const float corr = __expf(m[i] - mnew);
            float psum = 0.f;
#pragma unroll
            for (int j = 0; j < 8; j++) {
                const float p = __expf(s[i][j] - mnew);  // exp(-inf)=0 masks
                s[i][j] = p;
                psum += p;
            }
            psum += __shfl_xor_sync(0xffffffffu, psum, 1);
            psum += __shfl_xor_sync(0xffffffffu, psum, 2);
            psum += __shfl_xor_sync(0xffffffffu, psum, 4);
            l[i] = l[i] * corr + psum;
            m[i] = mnew;
#pragma unroll
            for (int j = 0; j < 8; j++) o[i][j] *= corr;

            // store P row (stride 68 floats = 272B, 16B aligned)
            *(float4*)(&P[(r0+i)*P_S + c0])     =
                make_float4(s[i][0], s[i][1], s[i][2], s[i][3]);
            *(float4*)(&P[(r0+i)*P_S + c0 + 4]) =
                make_float4(s[i][4], s[i][5], s[i][6], s[i][7]);
        }
        __syncthreads();

        // O[4][8] += P[4 rows][:] @ V[:][8 cols]   (kk in chunks of 4)
#pragma unroll 2
        for (int kk0 = 0; kk0 < 64; kk0 += 4) {
            float4 pr[4];
#pragma unroll
            for (int i = 0; i < 4; i++)
                pr[i] = *(const float4*)(&P[(r0+i)*P_S + kk0]);
#pragma unroll
            for (int t = 0; t < 4; t++) {
                const int kk = kk0 + t;
                float4 v0 = *(const float4*)(&Vs[kk*VS_S + c0]);
                float4 v1 = *(const float4*)(&Vs[kk*VS_S + c0 + 4]);
                const float vv[8] = {v0.x, v0.y, v0.z, v0.w,
                                     v1.x, v1.y, v1.z, v1.w};
                const float pv[4] = {
                    t == 0 ? pr[0].x : t == 1 ? pr[0].y : t == 2 ? pr[0].z : pr[0].w,
                    t == 0 ? pr[1].x : t == 1 ? pr[1].y : t == 2 ? pr[1].z : pr[1].w,
                    t == 0 ? pr[2].x : t == 1 ? pr[2].y : t == 2 ? pr[2].z : pr[2].w,
                    t == 0 ? pr[3].x : t == 1 ? pr[3].y : t == 2 ? pr[3].z : pr[3].w};
#pragma unroll
                for (int i = 0; i < 4; i++)
#pragma unroll
                    for (int j = 0; j < 8; j++) o[i][j] += pv[i] * vv[j];
            }
        }
    }

#pragma unroll
    for (int i = 0; i < 4; i++) {
        const float inv = 1.f / l[i];
        float* yp = Y + base + (size_t)(qt*128 + r0 + i)*CDIM + c0;
        *(float4*)(yp)     = make_float4(o[i][0]*inv, o[i][1]*inv,
                                         o[i][2]*inv, o[i][3]*inv);
        *(float4*)(yp + 4) = make_float4(o[i][4]*inv, o[i][5]*inv,
                                         o[i][6]*inv, o[i][7]*inv);
    }
}

// ---------------------------------------------------------------------------
extern "C" void kernel_launch(void* const* d_in, const int* in_sizes, int n_in,
                              void* d_out, int out_size) {
    const float* x  = (const float*)d_in[0];
    const float* Wq = (const float*)d_in[1];
    const float* bq = (const float*)d_in[2];
    const float* Wk = (const float*)d_in[3];
    const float* bk = (const float*)d_in[4];
    const float* Wv = (const float*)d_in[5];
    const float* bv = (const float*)d_in[6];
    const float* Wo = (const float*)d_in[7];
    const float* bo = (const float*)d_in[8];
    const float* Wc = (const float*)d_in[9];
    float* out = (float*)d_out;

    float *wqc, *bqc, *qc, *kb, *vb, *yb;
    cudaGetSymbolAddress((void**)&wqc, g_Wqc);
    cudaGetSymbolAddress((void**)&bqc, g_bqc);
    cudaGetSymbolAddress((void**)&qc,  g_qc);
    cudaGetSymbolAddress((void**)&kb,  g_k);
    cudaGetSymbolAddress((void**)&vb,  g_v);
    cudaGetSymbolAddress((void**)&yb,  g_y);

    cudaFuncSetAttribute(flash_attn,
                         cudaFuncAttributeMaxDynamicSharedMemorySize,
                         FLASH_SMEM);

    prep_wqc<<<(CDIM*CDIM)/256, 256>>>(Wq, Wc);
    prep_bqc<<<CDIM/256, 256>>>(bq, Wc);

    dim3 gg(CDIM/128, MROWS/128);   // (8, 32)
    sgemm_bias<<<gg, 256>>>(x, wqc, bqc, qc, MROWS, CDIM, CDIM);
    sgemm_bias<<<gg, 256>>>(x, Wk,  bk,  kb, MROWS, CDIM, CDIM);
    sgemm_bias<<<gg, 256>>>(x, Wv,  bv,  vb, MROWS, CDIM, CDIM);

    flash_attn<<<dim3(TDIM/128, BDIM*HN), 256, FLASH_SMEM>>>(qc, kb, vb, yb);

    sgemm_bias<<<gg, 256>>>(yb, Wo, bo, out, MROWS, CDIM, CDIM);
}